// round 17
// baseline (speedup 1.0000x reference)
#include <cuda_runtime.h>
#include <cuda_fp16.h>
#include <math.h>
#include <stdint.h>

// ---------------- problem constants ----------------
#define M_TOT   16384
#define SEQ     8192
#define KDIM    1024
#define HDIM    1024
#define RANK    16
#define CHUNK   256
#define NCH     32
#define NBATCH  2
#define NBC     64
#define LRC     0.02f
#define SCALE   2.0f
#define CLIP    1.0f
#define LN_EPS  1e-5f

// ---------------- fp16 GEMM tiling (BK=64) ----------------
#define BM 128
#define BN 128
#define BK 64
#define ROW_B 144
#define A_REGION (BM * ROW_B)
#define STAGE_BYTES_H ((BM + BN) * ROW_B)
#define NSTAGE 3
#define SMEM_GEMM (NSTAGE * STAGE_BYTES_H)       // 110592 B
#define NIT (KDIM / BK)                          // 16

// proj/mid fp16 kernels
#define PROW_B 80
#define PROJ_TILE (128 * PROW_B)
#define SMEM_PROJ (2 * 2 * PROJ_TILE)
#define SMEM_MID  (2 * PROJ_TILE)
#define PNIT (KDIM / 32)

// delta mma kernel
#define DROWS 64                                 // i-rows per stage
#define DROW_B 272                               // 128 halves + 16B pad (16B aligned)
#define DTILE (DROWS * DROW_B)                   // 17408
#define DPROW 48                                 // P row: 16 halves + pad (16B aligned)
#define DP_BYTES (CHUNK * DPROW)                 // 12288
#define SMEM_DELTA (3 * DTILE + DP_BYTES)        // 64512

// ---------------- device scratch ----------------
__device__ __align__(128) __half g_x_h      [M_TOT * KDIM];
__device__ __align__(128) __half g_shifted_h[M_TOT * KDIM];
__device__ __align__(128) __half g_V_h      [M_TOT * KDIM];
__device__ __align__(128) __half g_Wb_h     [HDIM * KDIM];
__device__ __align__(128) __half g_Wp_h     [HDIM * KDIM];
__device__ __align__(128) __half g_iB_h    [RANK * KDIM];
__device__ __align__(128) __half g_iA_t_h  [RANK * KDIM];
__device__ __align__(128) __half g_Beff_h  [NBC * RANK * KDIM];
__device__ __align__(128) float g_proj_in [NBC * CHUNK * RANK];
__device__ __align__(128) float g_proj_err[NBC * CHUNK * RANK];
__device__ __align__(128) float g_dA  [NBC * HDIM * RANK];
__device__ __align__(128) float g_dB  [NBC * RANK * KDIM];
__device__ __align__(128) float g_Aeff[NBC * HDIM * RANK];
__device__ __align__(128) float g_mid [M_TOT * RANK];

// ---------------- helpers ----------------
__device__ __forceinline__ uint32_t smem_u32(const void* p) {
    uint32_t a;
    asm("{ .reg .u64 t; cvta.to.shared.u64 t, %1; cvt.u32.u64 %0, t; }" : "=r"(a) : "l"(p));
    return a;
}
__device__ __forceinline__ void cp16(uint32_t d, const void* s) {
    asm volatile("cp.async.cg.shared.global [%0], [%1], 16;" :: "r"(d), "l"(s));
}
__device__ __forceinline__ void mma_f16(float4& c, const uint32_t a[4], const uint32_t b[2]) {
    asm volatile(
        "mma.sync.aligned.m16n8k16.row.col.f32.f16.f16.f32 "
        "{%0,%1,%2,%3}, {%4,%5,%6,%7}, {%8,%9}, {%0,%1,%2,%3};"
        : "+f"(c.x), "+f"(c.y), "+f"(c.z), "+f"(c.w)
        : "r"(a[0]), "r"(a[1]), "r"(a[2]), "r"(a[3]), "r"(b[0]), "r"(b[1]));
}
__device__ __forceinline__ void ldsm4(uint32_t r[4], uint32_t addr) {
    asm volatile("ldmatrix.sync.aligned.m8n8.x4.shared.b16 {%0,%1,%2,%3}, [%4];"
                 : "=r"(r[0]), "=r"(r[1]), "=r"(r[2]), "=r"(r[3]) : "r"(addr));
}
__device__ __forceinline__ void ldsm4t(uint32_t r[4], uint32_t addr) {
    asm volatile("ldmatrix.sync.aligned.m8n8.x4.trans.shared.b16 {%0,%1,%2,%3}, [%4];"
                 : "=r"(r[0]), "=r"(r[1]), "=r"(r[2]), "=r"(r[3]) : "r"(addr));
}
__device__ __forceinline__ uint32_t packh2(float x, float y) {
    __half2 h = __floats2half2_rn(x, y);
    return *reinterpret_cast<uint32_t*>(&h);
}

// ---------------- kernel 0: merged conversions (Wb | Wp | iB | iA^T) ----------------
__global__ __launch_bounds__(256) void conv_merged_kernel(
    const float* __restrict__ Wb, const float* __restrict__ Wp,
    const float* __restrict__ iB, const float* __restrict__ iA)
{
    int b = blockIdx.x;
    if (b >= 1032) {   // iA transpose: [K,R] -> fp16 [R,K], 8 blocks x 2048
        int o = (b - 1032) * 2048 + threadIdx.x * 8;
        int r = o >> 10, k = o & (KDIM - 1);
        __half tmp[8];
        #pragma unroll
        for (int j = 0; j < 8; j++)
            tmp[j] = __float2half(iA[(size_t)(k + j) * RANK + r]);
        *(uint4*)(g_iA_t_h + (size_t)r * KDIM + k) = *(uint4*)tmp;
        return;
    }
    const float* s;
    __half* d;
    int base;
    if (b < 512)       { s = Wb; d = g_Wb_h; base = b; }
    else if (b < 1024) { s = Wp; d = g_Wp_h; base = b - 512; }
    else               { s = iB; d = g_iB_h; base = b - 1024; }
    int i = base * 256 + threadIdx.x;
    float4 v0 = ((const float4*)s)[2 * i];
    float4 v1 = ((const float4*)s)[2 * i + 1];
    uint4 o;
    o.x = packh2(v0.x, v0.y);
    o.y = packh2(v0.z, v0.w);
    o.z = packh2(v1.x, v1.y);
    o.w = packh2(v1.z, v1.w);
    ((uint4*)d)[i] = o;
}

// ---------------- kernel 1: LayerNorm + shift (fp16) + x->fp16 ----------------
__global__ __launch_bounds__(256) void ln_shift_kernel(
    const float* __restrict__ x,
    const float* __restrict__ gam,
    const float* __restrict__ bet)
{
    int row = blockIdx.x;
    int s   = row & (SEQ - 1);
    const float4* xr = (const float4*)(x + (size_t)row * KDIM);
    float4 v = xr[threadIdx.x];

    {
        uint2* d = (uint2*)(g_x_h + (size_t)row * KDIM);
        d[threadIdx.x] = make_uint2(packh2(v.x, v.y), packh2(v.z, v.w));
    }

    float sum = v.x + v.y + v.z + v.w;
    float ssq = v.x*v.x + v.y*v.y + v.z*v.z + v.w*v.w;
    #pragma unroll
    for (int o = 16; o; o >>= 1) {
        sum += __shfl_xor_sync(0xffffffffu, sum, o);
        ssq += __shfl_xor_sync(0xffffffffu, ssq, o);
    }
    __shared__ float s1[8], s2[8];
    int w = threadIdx.x >> 5, l = threadIdx.x & 31;
    if (!l) { s1[w] = sum; s2[w] = ssq; }
    __syncthreads();
    if (threadIdx.x == 0) {
        float a = 0.f, b = 0.f;
        #pragma unroll
        for (int i = 0; i < 8; i++) { a += s1[i]; b += s2[i]; }
        s1[0] = a; s2[0] = b;
    }
    __syncthreads();
    float mu   = s1[0] * (1.0f / KDIM);
    float var  = s2[0] * (1.0f / KDIM) - mu * mu;
    float rstd = rsqrtf(var + LN_EPS);

    if (s == 0) {
        uint2* d = (uint2*)(g_shifted_h + ((size_t)row + SEQ - 1) * KDIM);
        d[threadIdx.x] = make_uint2(0u, 0u);
    } else {
        float4 g4 = ((const float4*)gam)[threadIdx.x];
        float4 b4 = ((const float4*)bet)[threadIdx.x];
        float ox = (v.x - mu) * rstd * g4.x + b4.x;
        float oy = (v.y - mu) * rstd * g4.y + b4.y;
        float oz = (v.z - mu) * rstd * g4.z + b4.z;
        float ow = (v.w - mu) * rstd * g4.w + b4.w;
        uint2* d = (uint2*)(g_shifted_h + (size_t)(row - 1) * KDIM);
        d[threadIdx.x] = make_uint2(packh2(ox, oy), packh2(oz, ow));
    }
}

// ---------------- kernel 2: FP16 mma GEMM (BK=64) ----------------
extern __shared__ float sm_dyn[];

__device__ __forceinline__ void gemm_load_stage_h(
    uint32_t sbase, int stage, const __half* Ah, const __half* Wh, int k0, int tid)
{
    uint32_t sa = sbase + stage * STAGE_BYTES_H;
    #pragma unroll
    for (int i = 0; i < 8; i++) {
        int idx = tid + i * 256;
        int row = idx >> 3;
        int seg = idx & 7;
        if (row < BM) {
            cp16(sa + row * ROW_B + seg * 16,
                 Ah + (size_t)row * KDIM + k0 + seg * 8);
        } else {
            int rb = row - BM;
            cp16(sa + A_REGION + rb * ROW_B + seg * 16,
                 Wh + (size_t)rb * KDIM + k0 + seg * 8);
        }
    }
    asm volatile("cp.async.commit_group;" ::: "memory");
}

__global__ __launch_bounds__(256, 2) void gemm_f16(
    float* __restrict__ out, int mode)
{
    const __half* A;
    const __half* W;
    if (mode == 0) { A = g_x_h;       W = g_Wb_h; }
    else           { A = g_shifted_h; W = g_Wp_h; }

    int tid  = threadIdx.x;
    int wid  = tid >> 5;
    int lane = tid & 31;
    int grp  = lane >> 2;
    int tig  = lane & 3;
    int wm   = wid & 1;
    int wn   = wid >> 1;

    int mbase = blockIdx.y * BM;
    int nbase = blockIdx.x * BN;
    const __half* Ab = A + (size_t)mbase * KDIM;
    const __half* Wb = W + (size_t)nbase * KDIM;

    uint32_t sbase = smem_u32(sm_dyn);

    int quad = lane >> 3, lr = lane & 7;
    uint32_t aOff = (uint32_t)(wm * 64 + ((quad & 1) << 3) + lr) * ROW_B +
                    ((quad >> 1) << 4);
    uint32_t bOff = (uint32_t)A_REGION +
                    (uint32_t)(wn * 32 + ((quad & 1) << 3) + lr) * ROW_B +
                    ((quad >> 1) << 4);

    float4 c[4][4];
    #pragma unroll
    for (int i = 0; i < 4; i++)
        #pragma unroll
        for (int j = 0; j < 4; j++) c[i][j] = make_float4(0.f, 0.f, 0.f, 0.f);

    gemm_load_stage_h(sbase, 0, Ab, Wb, 0, tid);
    gemm_load_stage_h(sbase, 1, Ab, Wb, BK, tid);

    for (int it = 0; it < NIT; it++) {
        if (it == NIT - 1) asm volatile("cp.async.wait_group 0;" ::: "memory");
        else               asm volatile("cp.async.wait_group 1;" ::: "memory");
        __syncthreads();
        if (it + 2 < NIT)
            gemm_load_stage_h(sbase, (it + 2) % NSTAGE, Ab, Wb, (it + 2) * BK, tid);

        uint32_t stge = sbase + (it % NSTAGE) * STAGE_BYTES_H;
        uint32_t aB = stge + aOff;
        uint32_t bB = stge + bOff;

        #pragma unroll
        for (int k16 = 0; k16 < 4; k16++) {
            uint32_t a[4][4], b[4][2];
            #pragma unroll
            for (int mf = 0; mf < 4; mf++)
                ldsm4(a[mf], aB + mf * (16 * ROW_B) + k16 * 32);
            #pragma unroll
            for (int p = 0; p < 2; p++) {
                uint32_t r[4];
                ldsm4(r, bB + p * (16 * ROW_B) + k16 * 32);
                b[2*p][0]   = r[0]; b[2*p][1]   = r[2];
                b[2*p+1][0] = r[1]; b[2*p+1][1] = r[3];
            }
            #pragma unroll
            for (int mf = 0; mf < 4; mf++)
                #pragma unroll
                for (int nf = 0; nf < 4; nf++)
                    mma_f16(c[mf][nf], a[mf], b[nf]);
        }
    }

    if (mode == 0) {
        const float* midp = g_mid + (size_t)mbase * RANK;
        const float* Ae   = g_Aeff + (size_t)(mbase >> 8) * (HDIM * RANK);
        uint32_t a[4][4], b[4][2];
        #pragma unroll
        for (int mf = 0; mf < 4; mf++) {
            int r0 = wm * 64 + mf * 16 + grp;
            const float* m0 = midp + (size_t)r0 * RANK;
            const float* m1 = midp + (size_t)(r0 + 8) * RANK;
            a[mf][0] = packh2(SCALE * m0[2*tig],     SCALE * m0[2*tig + 1]);
            a[mf][1] = packh2(SCALE * m1[2*tig],     SCALE * m1[2*tig + 1]);
            a[mf][2] = packh2(SCALE * m0[8 + 2*tig], SCALE * m0[8 + 2*tig + 1]);
            a[mf][3] = packh2(SCALE * m1[8 + 2*tig], SCALE * m1[8 + 2*tig + 1]);
        }
        #pragma unroll
        for (int nf = 0; nf < 4; nf++) {
            int col = nbase + wn * 32 + nf * 8 + grp;
            const float* ap = Ae + (size_t)col * RANK;
            b[nf][0] = packh2(ap[2*tig],     ap[2*tig + 1]);
            b[nf][1] = packh2(ap[8 + 2*tig], ap[8 + 2*tig + 1]);
        }
        #pragma unroll
        for (int mf = 0; mf < 4; mf++)
            #pragma unroll
            for (int nf = 0; nf < 4; nf++)
                mma_f16(c[mf][nf], a[mf], b[nf]);

        #pragma unroll
        for (int mf = 0; mf < 4; mf++) {
            int row0 = mbase + wm * 64 + mf * 16 + grp;
            #pragma unroll
            for (int nf = 0; nf < 4; nf++) {
                int col = nbase + wn * 32 + nf * 8 + 2 * tig;
                *(float2*)(out + (size_t)row0 * HDIM + col)       = make_float2(c[mf][nf].x, c[mf][nf].y);
                *(float2*)(out + (size_t)(row0 + 8) * HDIM + col) = make_float2(c[mf][nf].z, c[mf][nf].w);
            }
        }
    } else {
        #pragma unroll
        for (int mf = 0; mf < 4; mf++) {
            int row0 = mbase + wm * 64 + mf * 16 + grp;
            #pragma unroll
            for (int nf = 0; nf < 4; nf++) {
                int col = nbase + wn * 32 + nf * 8 + 2 * tig;
                *(uint32_t*)(g_V_h + (size_t)row0 * HDIM + col)       = packh2(c[mf][nf].x, c[mf][nf].y);
                *(uint32_t*)(g_V_h + (size_t)(row0 + 8) * HDIM + col) = packh2(c[mf][nf].z, c[mf][nf].w);
            }
        }
    }
}

// ---------------- kernel 3: proj via fp16 mma ----------------
__global__ __launch_bounds__(256) void proj_f16_kernel()
{
    int tid  = threadIdx.x;
    int wid  = tid >> 5;
    int lane = tid & 31;
    int grp  = lane >> 2;
    int tig  = lane & 3;

    int rowbase = blockIdx.x * 128;
    const __half* Xb = g_x_h + (size_t)rowbase * KDIM;
    const __half* Vb = g_V_h + (size_t)rowbase * KDIM;

    float4 cI[2], cE[2];
    cI[0] = make_float4(0,0,0,0); cI[1] = make_float4(0,0,0,0);
    cE[0] = make_float4(0,0,0,0); cE[1] = make_float4(0,0,0,0);

    uint32_t sbase = smem_u32(sm_dyn);

    auto load_stage = [&](int stage, int k0) {
        uint32_t sx = sbase + stage * (2 * PROJ_TILE);
        #pragma unroll
        for (int i = 0; i < 4; i++) {
            int idx = tid + i * 256;
            int row = idx >> 2;
            int seg = idx & 3;
            if (row < 128)
                cp16(sx + row * PROW_B + seg * 16, Xb + (size_t)row * KDIM + k0 + seg * 8);
            else
                cp16(sx + PROJ_TILE + (row - 128) * PROW_B + seg * 16,
                     Vb + (size_t)(row - 128) * KDIM + k0 + seg * 8);
        }
        asm volatile("cp.async.commit_group;" ::: "memory");
    };

    load_stage(0, 0);

    int quad = lane >> 3, lr = lane & 7;
    uint32_t aOff = (uint32_t)(wid * 16 + ((quad & 1) << 3) + lr) * PROW_B +
                    ((quad >> 1) << 4);

    for (int it = 0; it < PNIT; it++) {
        int k0 = it * 32;
        uint32_t bI[2][2][2], bE[2][2][2];
        #pragma unroll
        for (int kk = 0; kk < 2; kk++) {
            int kb = k0 + kk * 16;
            #pragma unroll
            for (int nf = 0; nf < 2; nf++) {
                int n = nf * 8 + grp;
                bI[kk][nf][0] = *(const uint32_t*)(g_iB_h   + (size_t)n * KDIM + kb + 2 * tig);
                bI[kk][nf][1] = *(const uint32_t*)(g_iB_h   + (size_t)n * KDIM + kb + 8 + 2 * tig);
                bE[kk][nf][0] = *(const uint32_t*)(g_iA_t_h + (size_t)n * KDIM + kb + 2 * tig);
                bE[kk][nf][1] = *(const uint32_t*)(g_iA_t_h + (size_t)n * KDIM + kb + 8 + 2 * tig);
            }
        }

        asm volatile("cp.async.wait_group 0;" ::: "memory");
        __syncthreads();
        if (it + 1 < PNIT) load_stage((it + 1) & 1, k0 + 32);

        uint32_t sx = sbase + (it & 1) * (2 * PROJ_TILE);
        uint32_t sv = sx + PROJ_TILE;

        #pragma unroll
        for (int kk = 0; kk < 2; kk++) {
            uint32_t ax[4], av[4];
            ldsm4(ax, sx + aOff + kk * 32);
            ldsm4(av, sv + aOff + kk * 32);
            #pragma unroll
            for (int nf = 0; nf < 2; nf++) {
                mma_f16(cI[nf], ax, bI[kk][nf]);
                mma_f16(cE[nf], av, bE[kk][nf]);
            }
        }
        __syncthreads();
    }

    int row = rowbase + wid * 16 + grp;
    #pragma unroll
    for (int nf = 0; nf < 2; nf++) {
        int col = nf * 8 + 2 * tig;
        *(float2*)(g_proj_in  + (size_t)row * RANK + col)       = make_float2(cI[nf].x, cI[nf].y);
        *(float2*)(g_proj_in  + (size_t)(row + 8) * RANK + col) = make_float2(cI[nf].z, cI[nf].w);
        *(float2*)(g_proj_err + (size_t)row * RANK + col)       = make_float2(cE[nf].x, cE[nf].y);
        *(float2*)(g_proj_err + (size_t)(row + 8) * RANK + col) = make_float2(cE[nf].z, cE[nf].w);
    }
}

// ---------------- kernel 4: delta via trans-ldmatrix mma ----------------
// mode 0: dA[c][h][r] = sum_i V[c,i,h] * P_in[c,i,r]
// mode 1: dB[c][r][k] = sum_i P_err[c,i,r] * x[c,i,k]
__global__ __launch_bounds__(256) void delta_mma_kernel()
{
    int c    = blockIdx.x;
    int blk  = blockIdx.y;      // 128-column block
    int mode = blockIdx.z;
    int tid  = threadIdx.x;
    int wid  = tid >> 5;
    int lane = tid & 31;
    int grp  = lane >> 2;
    int tig  = lane & 3;
    int quad = lane >> 3, lr = lane & 7;

    const __half* src = (mode == 0 ? g_V_h : g_x_h) + (size_t)c * CHUNK * KDIM + blk * 128;
    const float*  P   = (mode == 0 ? g_proj_in : g_proj_err) + (size_t)c * CHUNK * RANK;

    uint32_t sbase = smem_u32(sm_dyn);
    uint32_t pbase = sbase + 3 * DTILE;
    char* smc = (char*)sm_dyn;

    // P -> fp16 smem [256][16], rows padded to 48B
    for (int i = tid; i < CHUNK * RANK / 2; i += 256) {   // 2048 half2
        int row = i >> 3, col2 = i & 7;
        float2 f = *(const float2*)(P + (size_t)row * RANK + col2 * 2);
        *(uint32_t*)(smc + 3 * DTILE + row * DPROW + col2 * 4) = packh2(f.x, f.y);
    }

    auto load_stage = [&](int stage, int i0) {
        uint32_t sx = sbase + stage * DTILE;
        #pragma unroll
        for (int j = 0; j < 4; j++) {
            int idx = tid + j * 256;      // 0..1023
            int row = idx >> 4;           // 0..63
            int seg = idx & 15;
            cp16(sx + row * DROW_B + seg * 16,
                 src + (size_t)(i0 + row) * KDIM + seg * 8);
        }
        asm volatile("cp.async.commit_group;" ::: "memory");
    };

    load_stage(0, 0);
    load_stage(1, DROWS);
    __syncthreads();   // P smem ready before compute

    float4 c0 = make_float4(0,0,0,0), c1 = make_float4(0,0,0,0);

    // trans-ldsm address components: quad -> (colblk = quad&1, kblk = quad>>1)
    uint32_t mOffBase = (uint32_t)(((quad >> 1) * 8 + lr) * DROW_B) +
                        (uint32_t)((wid * 16 + (quad & 1) * 8) * 2);
    uint32_t pOffBase = (uint32_t)(((quad >> 1) * 8 + lr) * DPROW) +
                        (uint32_t)((quad & 1) * 16);

    const int NSTEPS = CHUNK / DROWS;   // 4 stages of 64 rows
    for (int s = 0; s < NSTEPS; s++) {
        if (s == NSTEPS - 1) asm volatile("cp.async.wait_group 0;" ::: "memory");
        else                 asm volatile("cp.async.wait_group 1;" ::: "memory");
        __syncthreads();
        if (s + 2 < NSTEPS) load_stage((s + 2) % 3, (s + 2) * DROWS);

        uint32_t mB = sbase + (s % 3) * DTILE + mOffBase;
        uint32_t pB = pbase + (uint32_t)(s * DROWS * DPROW) + pOffBase;

        #pragma unroll
        for (int j = 0; j < 4; j++) {       // 4 k16-steps per stage
            uint32_t fm[4], fp[4];
            ldsm4t(fm, mB + j * (16 * DROW_B));
            ldsm4t(fp, pB + j * (16 * DPROW));
            if (mode == 0) {
                uint32_t b0[2] = {fp[0], fp[2]};
                uint32_t b1[2] = {fp[1], fp[3]};
                mma_f16(c0, fm, b0);
                mma_f16(c1, fm, b1);
            } else {
                uint32_t b0[2] = {fm[0], fm[2]};
                uint32_t b1[2] = {fm[1], fm[3]};
                mma_f16(c0, fp, b0);
                mma_f16(c1, fp, b1);
            }
        }
    }

    if (mode == 0) {
        int h = blk * 128 + wid * 16 + grp;
        float* d = g_dA + (size_t)c * (HDIM * RANK);
        *(float2*)(d + (size_t)h * RANK + 2 * tig)           = make_float2(c0.x, c0.y);
        *(float2*)(d + (size_t)(h + 8) * RANK + 2 * tig)     = make_float2(c0.z, c0.w);
        *(float2*)(d + (size_t)h * RANK + 8 + 2 * tig)       = make_float2(c1.x, c1.y);
        *(float2*)(d + (size_t)(h + 8) * RANK + 8 + 2 * tig) = make_float2(c1.z, c1.w);
    } else {
        int k0 = blk * 128 + wid * 16;
        float* d = g_dB + (size_t)c * (RANK * KDIM);
        *(float2*)(d + (size_t)grp * KDIM + k0 + 2 * tig)           = make_float2(c0.x, c0.y);
        *(float2*)(d + (size_t)(grp + 8) * KDIM + k0 + 2 * tig)     = make_float2(c0.z, c0.w);
        *(float2*)(d + (size_t)grp * KDIM + k0 + 8 + 2 * tig)       = make_float2(c1.x, c1.y);
        *(float2*)(d + (size_t)(grp + 8) * KDIM + k0 + 8 + 2 * tig) = make_float2(c1.z, c1.w);
    }
}

// ---------------- kernel 5: exclusive cumsum over chunks ----------------
__global__ __launch_bounds__(256) void cumsum_kernel()
{
    int e = blockIdx.x * 256 + threadIdx.x;
    int b = blockIdx.y;
    float* base = blockIdx.z ? g_dB : g_dA;
    float run = 0.f;
    #pragma unroll
    for (int j = 0; j < NCH; j++) {
        size_t off = ((size_t)(b * NCH + j)) * (HDIM * RANK) + e;
        float t = base[off];
        base[off] = run;
        run += t;
    }
}

// ---------------- kernel 6: fused clip + effective weights ----------------
__global__ __launch_bounds__(256) void clip_eff_kernel(
    const float* __restrict__ iA, const float* __restrict__ iB)
{
    int c = blockIdx.x;
    const float* A = g_dA + (size_t)c * (HDIM * RANK);
    const float* B = g_dB + (size_t)c * (RANK * KDIM);
    float s = 0.f;
    for (int i = threadIdx.x; i < HDIM * RANK; i += 256) {
        float a = A[i]; s += a * a;
        float b = B[i]; s += b * b;
    }
    #pragma unroll
    for (int o = 16; o; o >>= 1) s += __shfl_xor_sync(0xffffffffu, s, o);
    __shared__ float sm[8];
    __shared__ float s_coef;
    int w = threadIdx.x >> 5, l = threadIdx.x & 31;
    if (!l) sm[w] = s;
    __syncthreads();
    if (threadIdx.x == 0) {
        float t = 0.f;
        #pragma unroll
        for (int i = 0; i < 8; i++) t += sm[i];
        float norm = LRC * sqrtf(t);
        s_coef = LRC * fminf(1.0f, CLIP / (norm + 1e-6f));
    }
    __syncthreads();
    float sc = s_coef;
    float* Ae = g_Aeff + (size_t)c * (HDIM * RANK);
    __half* Beh = g_Beff_h + (size_t)c * (RANK * KDIM);
    for (int i = threadIdx.x; i < HDIM * RANK; i += 256) {
        Ae[i]  = iA[i] - sc * A[i];
        Beh[i] = __float2half(iB[i] - sc * B[i]);
    }
}

// ---------------- kernel 7: mid = x_h @ Beff_h^T via fp16 mma ----------------
__global__ __launch_bounds__(256) void mid_f16_kernel()
{
    int tid  = threadIdx.x;
    int wid  = tid >> 5;
    int lane = tid & 31;
    int grp  = lane >> 2;
    int tig  = lane & 3;

    int rowbase = blockIdx.x * 128;
    int c = rowbase >> 8;
    const __half* Xb = g_x_h + (size_t)rowbase * KDIM;
    const __half* Beh = g_Beff_h + (size_t)c * (RANK * KDIM);

    float4 cI[2];
    cI[0] = make_float4(0,0,0,0); cI[1] = make_float4(0,0,0,0);

    uint32_t sbase = smem_u32(sm_dyn);

    auto load_stage = [&](int stage, int k0) {
        uint32_t sx = sbase + stage * PROJ_TILE;
        #pragma unroll
        for (int i = 0; i < 2; i++) {
            int idx = tid + i * 256;
            int row = idx >> 2;
            int seg = idx & 3;
            cp16(sx + row * PROW_B + seg * 16, Xb + (size_t)row * KDIM + k0 + seg * 8);
        }
        asm volatile("cp.async.commit_group;" ::: "memory");
    };

    load_stage(0, 0);

    int quad = lane >> 3, lr = lane & 7;
    uint32_t aOff = (uint32_t)(wid * 16 + ((quad & 1) << 3) + lr) * PROW_B +
                    ((quad >> 1) << 4);

    for (int it = 0; it < PNIT; it++) {
        int k0 = it * 32;
        uint32_t bI[2][2][2];
        #pragma unroll
        for (int kk = 0; kk < 2; kk++) {
            int kb = k0 + kk * 16;
            #pragma unroll
            for (int nf = 0; nf < 2; nf++) {
                int n = nf * 8 + grp;
                bI[kk][nf][0] = *(const uint32_t*)(Beh + (size_t)n * KDIM + kb + 2 * tig);
                bI[kk][nf][1] = *(const uint32_t*)(Beh + (size_t)n * KDIM + kb + 8 + 2 * tig);
            }
        }

        asm volatile("cp.async.wait_group 0;" ::: "memory");
        __syncthreads();
        if (it + 1 < PNIT) load_stage((it + 1) & 1, k0 + 32);

        uint32_t sx = sbase + (it & 1) * PROJ_TILE;

        #pragma unroll
        for (int kk = 0; kk < 2; kk++) {
            uint32_t ax[4];
            ldsm4(ax, sx + aOff + kk * 32);
            #pragma unroll
            for (int nf = 0; nf < 2; nf++)
                mma_f16(cI[nf], ax, bI[kk][nf]);
        }
        __syncthreads();
    }

    int row = rowbase + wid * 16 + grp;
    #pragma unroll
    for (int nf = 0; nf < 2; nf++) {
        int col = nf * 8 + 2 * tig;
        *(float2*)(g_mid + (size_t)row * RANK + col)       = make_float2(cI[nf].x, cI[nf].y);
        *(float2*)(g_mid + (size_t)(row + 8) * RANK + col) = make_float2(cI[nf].z, cI[nf].w);
    }
}

// ---------------- launch ----------------
extern "C" void kernel_launch(void* const* d_in, const int* in_sizes, int n_in,
                              void* d_out, int out_size)
{
    const float* x   = (const float*)d_in[0];
    const float* Wb  = (const float*)d_in[1];
    const float* iA  = (const float*)d_in[2];
    const float* iB  = (const float*)d_in[3];
    const float* gam = (const float*)d_in[4];
    const float* bet = (const float*)d_in[5];
    const float* Wp  = (const float*)d_in[6];
    float* out = (float*)d_out;

    cudaFuncSetAttribute(gemm_f16,         cudaFuncAttributeMaxDynamicSharedMemorySize, SMEM_GEMM);
    cudaFuncSetAttribute(proj_f16_kernel,  cudaFuncAttributeMaxDynamicSharedMemorySize, SMEM_PROJ);
    cudaFuncSetAttribute(mid_f16_kernel,   cudaFuncAttributeMaxDynamicSharedMemorySize, SMEM_MID);
    cudaFuncSetAttribute(delta_mma_kernel, cudaFuncAttributeMaxDynamicSharedMemorySize, SMEM_DELTA);

    conv_merged_kernel<<<1040, 256>>>(Wb, Wp, iB, iA);
    ln_shift_kernel<<<M_TOT, 256>>>(x, gam, bet);

    dim3 gg(HDIM / BN, M_TOT / BM);
    gemm_f16<<<gg, 256, SMEM_GEMM>>>(nullptr, 1);             // V_h = shifted @ Wp^T
    proj_f16_kernel<<<M_TOT / 128, 256, SMEM_PROJ>>>();
    delta_mma_kernel<<<dim3(NBC, KDIM / 128, 2), 256, SMEM_DELTA>>>();
    cumsum_kernel<<<dim3((HDIM * RANK) / 256, NBATCH, 2), 256>>>();
    clip_eff_kernel<<<NBC, 256>>>(iA, iB);
    mid_f16_kernel<<<M_TOT / 128, 256, SMEM_MID>>>();
    gemm_f16<<<gg, 256, SMEM_GEMM>>>(out, 0);                 // out = x @ Wb^T + lora
}